// round 1
// baseline (speedup 1.0000x reference)
#include <cuda_runtime.h>
#include <cuda_bf16.h>
#include <math_constants.h>

// Problem constants
#define N_TOK     16384
#define D_MODEL   2048
#define N_EXP     64
#define TOPK      4

// Output layout (fp32 elements)
#define OFF_TOPK_I  0
#define OFF_TOPK_S  (N_TOK * TOPK)                 // 65536
#define OFF_SCORES  (2 * N_TOK * TOPK)             // 131072
#define OFF_AUX     (OFF_SCORES + N_TOK * N_EXP)   // 1179648

// GEMM tiling
#define TILE_M  128
#define KC      16
#define NC      (D_MODEL / KC)    // 128 chunks
#define UPAD    20                // row pad for u smem (float4-aligned, conflict-free reads w/ strided tokens)

__device__ float g_expert_sum[N_EXP];

struct SmemG {
    float us[2][TILE_M][UPAD];    // [buf][token][k]   2*128*20*4 = 20480 B
    float es[2][KC][N_EXP];       // [buf][k][expert]  2*16*64*4  =  8192 B
};
struct SmemE {
    float logits[TILE_M][N_EXP + 1];  // 128*65*4 = 33280 B
    float rsum[TILE_M];
    float csum[TILE_M];
};
union Smem {
    SmemG g;
    SmemE e;
};

__global__ void __launch_bounds__(128, 1)
router_zero_kernel() {
    g_expert_sum[threadIdx.x] = 0.0f;
}

__global__ void __launch_bounds__(128, 1)
router_main_kernel(const float* __restrict__ u,
                   const float* __restrict__ E,
                   const float* __restrict__ bias,
                   float* __restrict__ out) {
    __shared__ Smem sm;

    const int tid = threadIdx.x;
    const int tx  = tid & 7;     // expert group: experts tx*8 .. tx*8+7
    const int ty  = tid >> 3;    // token group : tokens ty + 16*i, i=0..7
    const int row0 = blockIdx.x * TILE_M;

    float acc[8][8];
#pragma unroll
    for (int i = 0; i < 8; i++)
#pragma unroll
        for (int j = 0; j < 8; j++) acc[i][j] = 0.0f;

    // bias for this thread's experts
    float bj[8];
#pragma unroll
    for (int j = 0; j < 8; j++) bj[j] = __ldg(&bias[tx * 8 + j]);

    // loader mapping
    const int u_lm  = tid >> 2;          // 0..31 (base token row)
    const int u_lk4 = tid & 3;           // which float4 of the 16-k chunk
    const int e_le4 = tid & 15;          // which float4 of the 64-expert row
    const int e_lk  = tid >> 4;          // 0..7 (k rows lk, lk+8)

    // ---- prologue: load chunk 0 into buf 0 ----
    {
#pragma unroll
        for (int r = 0; r < 4; r++) {
            int m = u_lm + 32 * r;
            float4 v = *reinterpret_cast<const float4*>(
                &u[(size_t)(row0 + m) * D_MODEL + u_lk4 * 4]);
            *reinterpret_cast<float4*>(&sm.g.us[0][m][u_lk4 * 4]) = v;
        }
#pragma unroll
        for (int rr = 0; rr < 2; rr++) {
            int k = e_lk + 8 * rr;
            float4 v = *reinterpret_cast<const float4*>(
                &E[(size_t)k * N_EXP + e_le4 * 4]);
            *reinterpret_cast<float4*>(&sm.g.es[0][k][e_le4 * 4]) = v;
        }
    }
    __syncthreads();

    int buf = 0;
    for (int c = 0; c < NC; c++) {
        // ---- issue global loads for chunk c+1 into registers ----
        float4 ru[4], re[2];
        const bool more = (c + 1 < NC);
        if (more) {
            const int kbase = (c + 1) * KC;
#pragma unroll
            for (int r = 0; r < 4; r++) {
                int m = u_lm + 32 * r;
                ru[r] = *reinterpret_cast<const float4*>(
                    &u[(size_t)(row0 + m) * D_MODEL + kbase + u_lk4 * 4]);
            }
#pragma unroll
            for (int rr = 0; rr < 2; rr++) {
                int k = e_lk + 8 * rr;
                re[rr] = *reinterpret_cast<const float4*>(
                    &E[(size_t)(kbase + k) * N_EXP + e_le4 * 4]);
            }
        }

        // ---- compute chunk c from smem buf ----
#pragma unroll
        for (int k = 0; k < KC; k++) {
            float4 b0 = *reinterpret_cast<const float4*>(&sm.g.es[buf][k][tx * 8]);
            float4 b1 = *reinterpret_cast<const float4*>(&sm.g.es[buf][k][tx * 8 + 4]);
            float bfrag[8] = {b0.x, b0.y, b0.z, b0.w, b1.x, b1.y, b1.z, b1.w};
            float afrag[8];
#pragma unroll
            for (int i = 0; i < 8; i++) afrag[i] = sm.g.us[buf][ty + 16 * i][k];
#pragma unroll
            for (int i = 0; i < 8; i++)
#pragma unroll
                for (int j = 0; j < 8; j++)
                    acc[i][j] = fmaf(afrag[i], bfrag[j], acc[i][j]);
        }

        // ---- store staged registers into the other buffer ----
        if (more) {
            int nb = buf ^ 1;
#pragma unroll
            for (int r = 0; r < 4; r++) {
                int m = u_lm + 32 * r;
                *reinterpret_cast<float4*>(&sm.g.us[nb][m][u_lk4 * 4]) = ru[r];
            }
#pragma unroll
            for (int rr = 0; rr < 2; rr++) {
                int k = e_lk + 8 * rr;
                *reinterpret_cast<float4*>(&sm.g.es[nb][k][e_le4 * 4]) = re[rr];
            }
        }
        __syncthreads();
        buf ^= 1;
    }

    // ================= epilogue =================
    // write logits (+bias) into smem (union repurposed; all smem reads done)
#pragma unroll
    for (int i = 0; i < 8; i++) {
        int m = ty + 16 * i;
#pragma unroll
        for (int j = 0; j < 8; j++)
            sm.e.logits[m][tx * 8 + j] = acc[i][j] + bj[j];
    }
    __syncthreads();

    // per-token softmax + stable top-4 (one thread per token)
    {
        const int t  = tid;
        const int gt = row0 + t;

        float v0 = -CUDART_INF_F, v1 = -CUDART_INF_F, v2 = -CUDART_INF_F, v3 = -CUDART_INF_F;
        int   i0 = 0, i1 = 0, i2 = 0, i3 = 0;
#pragma unroll 8
        for (int e = 0; e < N_EXP; e++) {
            float l = sm.e.logits[t][e];
            if (l > v3) {
                if (l > v0)      { v3 = v2; i3 = i2; v2 = v1; i2 = i1; v1 = v0; i1 = i0; v0 = l; i0 = e; }
                else if (l > v1) { v3 = v2; i3 = i2; v2 = v1; i2 = i1; v1 = l; i1 = e; }
                else if (l > v2) { v3 = v2; i3 = i2; v2 = l;  i2 = e; }
                else             { v3 = l;  i3 = e; }
            }
        }
        const float mx = v0;
        float s = 0.0f;
#pragma unroll 8
        for (int e = 0; e < N_EXP; e++) {
            float ex = __expf(sm.e.logits[t][e] - mx);
            s += ex;
            sm.e.logits[t][e] = ex;   // in-place: this thread owns row t
        }
        const float rs = 1.0f / s;
        sm.e.rsum[t] = rs;

        // top-k outputs (indices as float)
        out[OFF_TOPK_I + gt * 4 + 0] = (float)i0;
        out[OFF_TOPK_I + gt * 4 + 1] = (float)i1;
        out[OFF_TOPK_I + gt * 4 + 2] = (float)i2;
        out[OFF_TOPK_I + gt * 4 + 3] = (float)i3;
        out[OFF_TOPK_S + gt * 4 + 0] = sm.e.logits[t][i0] * rs;
        out[OFF_TOPK_S + gt * 4 + 1] = sm.e.logits[t][i1] * rs;
        out[OFF_TOPK_S + gt * 4 + 2] = sm.e.logits[t][i2] * rs;
        out[OFF_TOPK_S + gt * 4 + 3] = sm.e.logits[t][i3] * rs;
    }
    __syncthreads();

    // coalesced scores store + per-expert partial sums (e = tid & 63, constant per thread)
    {
        float csum = 0.0f;
        const int base = blockIdx.x * (TILE_M * N_EXP);
#pragma unroll 4
        for (int it = 0; it < (TILE_M * N_EXP) / 128; it++) {
            int idx = it * 128 + tid;
            int t   = idx >> 6;
            int e   = idx & 63;
            float val = sm.e.logits[t][e] * sm.e.rsum[t];
            out[OFF_SCORES + base + idx] = val;
            csum += val;
        }
        sm.e.csum[tid] = csum;
        __syncthreads();
        if (tid < N_EXP)
            atomicAdd(&g_expert_sum[tid], sm.e.csum[tid] + sm.e.csum[tid + 64]);
    }
}

__global__ void __launch_bounds__(64, 1)
router_aux_kernel(float* __restrict__ out) {
    __shared__ float p[N_EXP];
    int e = threadIdx.x;
    float m = g_expert_sum[e] * (1.0f / (float)N_TOK);
    p[e] = m * m;
    __syncthreads();
    if (e == 0) {
        float s = 0.0f;
#pragma unroll
        for (int i = 0; i < N_EXP; i++) s += p[i];
        out[OFF_AUX] = s * (float)N_EXP;
    }
}

extern "C" void kernel_launch(void* const* d_in, const int* in_sizes, int n_in,
                              void* d_out, int out_size) {
    const float* u    = (const float*)d_in[0];
    const float* E    = (const float*)d_in[1];
    const float* bias = (const float*)d_in[2];
    float* out = (float*)d_out;

    router_zero_kernel<<<1, 64>>>();
    router_main_kernel<<<N_TOK / TILE_M, 128>>>(u, E, bias, out);
    router_aux_kernel<<<1, 64>>>(out);
}

// round 2
// speedup vs baseline: 1.2414x; 1.2414x over previous
#include <cuda_runtime.h>
#include <cuda_bf16.h>
#include <math_constants.h>

// Problem constants
#define N_TOK     16384
#define D_MODEL   2048
#define N_EXP     64
#define TOPK      4

// Output layout (fp32 elements)
#define OFF_TOPK_I  0
#define OFF_TOPK_S  (N_TOK * TOPK)                 // 65536
#define OFF_SCORES  (2 * N_TOK * TOPK)             // 131072
#define OFF_AUX     (OFF_SCORES + N_TOK * N_EXP)   // 1179648

// GEMM tiling
#define TILE_M  128
#define KC      16
#define NC      (D_MODEL / KC)    // 128 chunks
#define UPAD    20                // row pad for u smem

// ---- packed f32x2 helpers (sm_103a) ----
#define PACK_DUP(d, x)    asm("mov.b64 %0, {%1, %1};" : "=l"(d) : "f"(x))
#define PACK2(d, x, y)    asm("mov.b64 %0, {%1, %2};" : "=l"(d) : "f"(x), "f"(y))
#define UNPACK2(lo, hi, v) asm("mov.b64 {%0, %1}, %2;" : "=f"(lo), "=f"(hi) : "l"(v))
#define FMA2(d, a, b)     asm("fma.rn.f32x2 %0, %1, %2, %0;" : "+l"(d) : "l"(a), "l"(b))

__device__ float g_expert_sum[N_EXP];

struct SmemG {
    float us[2][TILE_M][UPAD];    // [buf][token][k]
    float es[2][KC][N_EXP];       // [buf][k][expert]
};
struct SmemE {
    float logits[TILE_M][N_EXP + 1];
    float rsum[TILE_M];
    float csum[TILE_M];
};
union Smem {
    SmemG g;
    SmemE e;
};

__global__ void __launch_bounds__(128, 1)
router_zero_kernel() {
    g_expert_sum[threadIdx.x & 63] = 0.0f;
}

__global__ void __launch_bounds__(128, 1)
router_main_kernel(const float* __restrict__ u,
                   const float* __restrict__ E,
                   const float* __restrict__ bias,
                   float* __restrict__ out) {
    __shared__ Smem sm;

    const int tid = threadIdx.x;
    const int tx  = tid & 7;     // expert group: experts tx*8 .. tx*8+7
    const int ty  = tid >> 3;    // token group : tokens ty + 16*i, i=0..7
    const int row0 = blockIdx.x * TILE_M;

    // 8 tokens x 4 expert-pairs, packed f32x2 accumulators
    unsigned long long acc2[8][4];
#pragma unroll
    for (int i = 0; i < 8; i++)
#pragma unroll
        for (int p = 0; p < 4; p++) acc2[i][p] = 0ULL;

    // bias for this thread's experts
    float bj[8];
#pragma unroll
    for (int j = 0; j < 8; j++) bj[j] = __ldg(&bias[tx * 8 + j]);

    // loader mapping
    const int u_lm  = tid >> 2;          // 0..31 (base token row)
    const int u_lk4 = tid & 3;           // which float4 of the 16-k chunk
    const int e_le4 = tid & 15;          // which float4 of the 64-expert row
    const int e_lk  = tid >> 4;          // 0..7 (k rows lk, lk+8)

    // ---- prologue: load chunk 0 into buf 0 ----
    {
#pragma unroll
        for (int r = 0; r < 4; r++) {
            int m = u_lm + 32 * r;
            float4 v = *reinterpret_cast<const float4*>(
                &u[(size_t)(row0 + m) * D_MODEL + u_lk4 * 4]);
            *reinterpret_cast<float4*>(&sm.g.us[0][m][u_lk4 * 4]) = v;
        }
#pragma unroll
        for (int rr = 0; rr < 2; rr++) {
            int k = e_lk + 8 * rr;
            float4 v = *reinterpret_cast<const float4*>(
                &E[(size_t)k * N_EXP + e_le4 * 4]);
            *reinterpret_cast<float4*>(&sm.g.es[0][k][e_le4 * 4]) = v;
        }
    }
    __syncthreads();

    int buf = 0;
    for (int c = 0; c < NC; c++) {
        // ---- issue global loads for chunk c+1 into registers ----
        float4 ru[4], re[2];
        const bool more = (c + 1 < NC);
        if (more) {
            const int kbase = (c + 1) * KC;
#pragma unroll
            for (int r = 0; r < 4; r++) {
                int m = u_lm + 32 * r;
                ru[r] = *reinterpret_cast<const float4*>(
                    &u[(size_t)(row0 + m) * D_MODEL + kbase + u_lk4 * 4]);
            }
#pragma unroll
            for (int rr = 0; rr < 2; rr++) {
                int k = e_lk + 8 * rr;
                re[rr] = *reinterpret_cast<const float4*>(
                    &E[(size_t)(kbase + k) * N_EXP + e_le4 * 4]);
            }
        }

        // ---- compute chunk c from smem buf (packed f32x2) ----
#pragma unroll
        for (int k = 0; k < KC; k++) {
            float4 b0 = *reinterpret_cast<const float4*>(&sm.g.es[buf][k][tx * 8]);
            float4 b1 = *reinterpret_cast<const float4*>(&sm.g.es[buf][k][tx * 8 + 4]);
            unsigned long long bp[4];
            PACK2(bp[0], b0.x, b0.y);
            PACK2(bp[1], b0.z, b0.w);
            PACK2(bp[2], b1.x, b1.y);
            PACK2(bp[3], b1.z, b1.w);

            unsigned long long ap[8];
#pragma unroll
            for (int i = 0; i < 8; i++) {
                float a = sm.g.us[buf][ty + 16 * i][k];
                PACK_DUP(ap[i], a);
            }
#pragma unroll
            for (int i = 0; i < 8; i++)
#pragma unroll
                for (int p = 0; p < 4; p++)
                    FMA2(acc2[i][p], ap[i], bp[p]);
        }

        // ---- store staged registers into the other buffer ----
        if (more) {
            int nb = buf ^ 1;
#pragma unroll
            for (int r = 0; r < 4; r++) {
                int m = u_lm + 32 * r;
                *reinterpret_cast<float4*>(&sm.g.us[nb][m][u_lk4 * 4]) = ru[r];
            }
#pragma unroll
            for (int rr = 0; rr < 2; rr++) {
                int k = e_lk + 8 * rr;
                *reinterpret_cast<float4*>(&sm.g.es[nb][k][e_le4 * 4]) = re[rr];
            }
        }
        __syncthreads();
        buf ^= 1;
    }

    // ================= epilogue =================
    // write logits (+bias) into smem
#pragma unroll
    for (int i = 0; i < 8; i++) {
        int m = ty + 16 * i;
#pragma unroll
        for (int p = 0; p < 4; p++) {
            float lo, hi;
            UNPACK2(lo, hi, acc2[i][p]);
            sm.e.logits[m][tx * 8 + 2 * p]     = lo + bj[2 * p];
            sm.e.logits[m][tx * 8 + 2 * p + 1] = hi + bj[2 * p + 1];
        }
    }
    __syncthreads();

    // per-token softmax + stable top-4 (one thread per token)
    {
        const int t  = tid;
        const int gt = row0 + t;

        float v0 = -CUDART_INF_F, v1 = -CUDART_INF_F, v2 = -CUDART_INF_F, v3 = -CUDART_INF_F;
        int   i0 = 0, i1 = 0, i2 = 0, i3 = 0;
#pragma unroll 8
        for (int e = 0; e < N_EXP; e++) {
            float l = sm.e.logits[t][e];
            if (l > v3) {
                if (l > v0)      { v3 = v2; i3 = i2; v2 = v1; i2 = i1; v1 = v0; i1 = i0; v0 = l; i0 = e; }
                else if (l > v1) { v3 = v2; i3 = i2; v2 = v1; i2 = i1; v1 = l; i1 = e; }
                else if (l > v2) { v3 = v2; i3 = i2; v2 = l;  i2 = e; }
                else             { v3 = l;  i3 = e; }
            }
        }
        const float mx = v0;
        float s = 0.0f;
#pragma unroll 8
        for (int e = 0; e < N_EXP; e++) {
            float ex = __expf(sm.e.logits[t][e] - mx);
            s += ex;
            sm.e.logits[t][e] = ex;
        }
        const float rs = 1.0f / s;
        sm.e.rsum[t] = rs;

        out[OFF_TOPK_I + gt * 4 + 0] = (float)i0;
        out[OFF_TOPK_I + gt * 4 + 1] = (float)i1;
        out[OFF_TOPK_I + gt * 4 + 2] = (float)i2;
        out[OFF_TOPK_I + gt * 4 + 3] = (float)i3;
        out[OFF_TOPK_S + gt * 4 + 0] = sm.e.logits[t][i0] * rs;
        out[OFF_TOPK_S + gt * 4 + 1] = sm.e.logits[t][i1] * rs;
        out[OFF_TOPK_S + gt * 4 + 2] = sm.e.logits[t][i2] * rs;
        out[OFF_TOPK_S + gt * 4 + 3] = sm.e.logits[t][i3] * rs;
    }
    __syncthreads();

    // coalesced scores store + per-expert partial sums
    {
        float csum = 0.0f;
        const int base = blockIdx.x * (TILE_M * N_EXP);
#pragma unroll 4
        for (int it = 0; it < (TILE_M * N_EXP) / 128; it++) {
            int idx = it * 128 + tid;
            int t   = idx >> 6;
            int e   = idx & 63;
            float val = sm.e.logits[t][e] * sm.e.rsum[t];
            out[OFF_SCORES + base + idx] = val;
            csum += val;
        }
        sm.e.csum[tid] = csum;
        __syncthreads();
        if (tid < N_EXP)
            atomicAdd(&g_expert_sum[tid], sm.e.csum[tid] + sm.e.csum[tid + 64]);
    }
}

__global__ void __launch_bounds__(64, 1)
router_aux_kernel(float* __restrict__ out) {
    __shared__ float p[N_EXP];
    int e = threadIdx.x;
    float m = g_expert_sum[e] * (1.0f / (float)N_TOK);
    p[e] = m * m;
    __syncthreads();
    if (e == 0) {
        float s = 0.0f;
#pragma unroll
        for (int i = 0; i < N_EXP; i++) s += p[i];
        out[OFF_AUX] = s * (float)N_EXP;
    }
}

extern "C" void kernel_launch(void* const* d_in, const int* in_sizes, int n_in,
                              void* d_out, int out_size) {
    const float* u    = (const float*)d_in[0];
    const float* E    = (const float*)d_in[1];
    const float* bias = (const float*)d_in[2];
    float* out = (float*)d_out;

    router_zero_kernel<<<1, 64>>>();
    router_main_kernel<<<N_TOK / TILE_M, 128>>>(u, E, bias, out);
    router_aux_kernel<<<1, 64>>>(out);
}